// round 1
// baseline (speedup 1.0000x reference)
#include <cuda_runtime.h>
#include <math.h>

// ---------------------------------------------------------------------------
// FSC loss: 8 x complex 128^3 FFT (ref + i*pred packing), per-shell power
// sums, fsc = num / (sqrt(d1*d2) + eps), loss = 1 - mean(fsc^2).
// ---------------------------------------------------------------------------

#define NPT 128
#define NSHELL 65           // 64 shells + overflow bin
#define PLANE_PAD 129       // 128 + 1 padding -> conflict-free both directions
#define SMEM_BYTES (2 * 128 * PLANE_PAD * 4)

static __device__ float2 g_fft[8u * 128u * 128u * 128u];   // 134 MB scratch
static __device__ double g_acc[8][NSHELL][3];              // num, d1, d2

__device__ __forceinline__ int rev7(int i) { return (int)(__brev((unsigned)i) >> 25); }

// One FFT pass over 128 lines of 128 points held in a padded smem plane.
// MODE 0: element addr = line*129 + i   (lines along padded rows)
// MODE 1: element addr = i*129 + line   (lines along columns)
template <int MODE>
__device__ void fft_pass(float* __restrict__ sRe, float* __restrict__ sIm,
                         const float* __restrict__ twr, const float* __restrict__ twi,
                         int tid)
{
    // bit-reversal permutation of every line
    for (int n = tid; n < 128 * 128; n += 256) {
        int line = n >> 7, i = n & 127;
        int j = rev7(i);
        if (i < j) {
            int a = (MODE == 0) ? line * PLANE_PAD + i : i * PLANE_PAD + line;
            int c = (MODE == 0) ? line * PLANE_PAD + j : j * PLANE_PAD + line;
            float t0 = sRe[a]; sRe[a] = sRe[c]; sRe[c] = t0;
            float t1 = sIm[a]; sIm[a] = sIm[c]; sIm[c] = t1;
        }
    }
    __syncthreads();

#pragma unroll
    for (int stage = 1; stage <= 7; stage++) {
        const int half  = 1 << (stage - 1);
        const int tstep = 128 >> stage;
        for (int n = tid; n < 128 * 64; n += 256) {
            int line = n >> 6, k = n & 63;
            int j = k & (half - 1);
            int p = ((k >> (stage - 1)) << stage) + j;
            int q = p + half;
            float wr = twr[j * tstep], wi = twi[j * tstep];
            int ia = (MODE == 0) ? line * PLANE_PAD + p : p * PLANE_PAD + line;
            int ib = (MODE == 0) ? line * PLANE_PAD + q : q * PLANE_PAD + line;
            float ur = sRe[ia], ui = sIm[ia];
            float vr = sRe[ib], vi = sIm[ib];
            float tr = vr * wr - vi * wi;
            float ti = vr * wi + vi * wr;
            sRe[ia] = ur + tr; sIm[ia] = ui + ti;
            sRe[ib] = ur - tr; sIm[ib] = ui - ti;
        }
        __syncthreads();
    }
}

// Kernel 1: per (b, x) plane [y][z]; load ref + i*pred, FFT along Z then Y,
// write complex result to scratch in the natural (b,x,y,z) layout.
__global__ __launch_bounds__(256, 1)
void k_fft_zy(const float* __restrict__ ref, const float* __restrict__ pred)
{
    extern __shared__ float sm[];
    float* sRe = sm;
    float* sIm = sm + 128 * PLANE_PAD;
    __shared__ float twr[64], twi[64];

    int tid = threadIdx.x;
    if (tid < 64) {
        double ang = -2.0 * 3.14159265358979323846 * (double)tid / 128.0;
        twr[tid] = (float)cos(ang);
        twi[tid] = (float)sin(ang);
    }
    int b = blockIdx.x >> 7;
    int x = blockIdx.x & 127;
    size_t base = ((size_t)(b * 128 + x)) << 14;   // *16384

    for (int n = tid; n < 16384; n += 256) {
        int y = n >> 7, z = n & 127;
        sRe[y * PLANE_PAD + z] = ref[base + n];
        sIm[y * PLANE_PAD + z] = pred[base + n];
    }
    __syncthreads();

    fft_pass<0>(sRe, sIm, twr, twi, tid);   // Z (lines = y)
    fft_pass<1>(sRe, sIm, twr, twi, tid);   // Y (lines = z)

    for (int n = tid; n < 16384; n += 256) {
        int y = n >> 7, z = n & 127;
        g_fft[base + n] = make_float2(sRe[y * PLANE_PAD + z], sIm[y * PLANE_PAD + z]);
    }
}

// Kernel 2: per (b, y) plane [x][z]; FFT along X, coalesced loads/stores over z.
__global__ __launch_bounds__(256, 1)
void k_fft_x()
{
    extern __shared__ float sm[];
    float* sRe = sm;
    float* sIm = sm + 128 * PLANE_PAD;
    __shared__ float twr[64], twi[64];

    int tid = threadIdx.x;
    if (tid < 64) {
        double ang = -2.0 * 3.14159265358979323846 * (double)tid / 128.0;
        twr[tid] = (float)cos(ang);
        twi[tid] = (float)sin(ang);
    }
    int b = blockIdx.x >> 7;
    int y = blockIdx.x & 127;
    size_t bbase = (size_t)b << 21;

    for (int n = tid; n < 16384; n += 256) {
        int x = n >> 7, z = n & 127;
        float2 v = g_fft[bbase + ((size_t)x << 14) + ((size_t)y << 7) + z];
        sRe[x * PLANE_PAD + z] = v.x;
        sIm[x * PLANE_PAD + z] = v.y;
    }
    __syncthreads();

    fft_pass<1>(sRe, sIm, twr, twi, tid);   // X (lines = z, elements = x)

    for (int n = tid; n < 16384; n += 256) {
        int x = n >> 7, z = n & 127;
        g_fft[bbase + ((size_t)x << 14) + ((size_t)y << 7) + z] =
            make_float2(sRe[x * PLANE_PAD + z], sIm[x * PLANE_PAD + z]);
    }
}

// Kernel 3: unpack F1/F2 from G(k), G(-k), accumulate per-shell sums.
__global__ __launch_bounds__(256)
void k_reduce(const int* __restrict__ shell)
{
    __shared__ float binN[NSHELL], binD1[NSHELL], binD2[NSHELL];
    int tid = threadIdx.x;
    if (tid < NSHELL) { binN[tid] = 0.f; binD1[tid] = 0.f; binD2[tid] = 0.f; }
    __syncthreads();

    int b = blockIdx.x >> 7;
    int x = blockIdx.x & 127;
    int nx = (128 - x) & 127;
    size_t bbase = (size_t)b << 21;

    for (int n = tid; n < 16384; n += 256) {
        int y = n >> 7, z = n & 127;
        int ny = (128 - y) & 127;
        int nz = (128 - z) & 127;
        float2 G  = g_fft[bbase + ((size_t)x  << 14) + n];
        float2 Gm = g_fft[bbase + ((size_t)nx << 14) + (ny << 7) + nz];
        // A = G(k) + conj(G(-k)) = 2*F1 ;  B = G(k) - conj(G(-k)) = 2i*F2
        float ar = G.x + Gm.x, ai = G.y - Gm.y;
        float br = G.x - Gm.x, bi = G.y + Gm.y;
        float cross = ar * bi - ai * br;     // ∝ Re(F1 conj F2)   (x4 scale)
        float p1 = ar * ar + ai * ai;        // ∝ |F1|^2           (x4 scale)
        float p2 = br * br + bi * bi;        // ∝ |F2|^2           (x4 scale)
        int s = shell[(x << 14) + n];
        atomicAdd(&binN[s],  cross);
        atomicAdd(&binD1[s], p1);
        atomicAdd(&binD2[s], p2);
    }
    __syncthreads();
    if (tid < NSHELL) {
        atomicAdd(&g_acc[b][tid][0], (double)binN[tid]);
        atomicAdd(&g_acc[b][tid][1], (double)binD1[tid]);
        atomicAdd(&g_acc[b][tid][2], (double)binD2[tid]);
    }
}

// Kernel 4: loss = 1 - mean_{b,s<64}(fsc^2)
__global__ __launch_bounds__(512)
void k_loss(float* __restrict__ out)
{
    __shared__ double ssum[512];
    int t = threadIdx.x;
    int b = t >> 6, s = t & 63;
    double num = g_acc[b][s][0];
    double d1  = g_acc[b][s][1];
    double d2  = g_acc[b][s][2];
    double fsc = num / (sqrt(d1 * d2) + 1e-8);
    ssum[t] = fsc * fsc;
    __syncthreads();
    for (int off = 256; off > 0; off >>= 1) {
        if (t < off) ssum[t] += ssum[t + off];
        __syncthreads();
    }
    if (t == 0) out[0] = (float)(1.0 - ssum[0] / 512.0);
}

extern "C" void kernel_launch(void* const* d_in, const int* in_sizes, int n_in,
                              void* d_out, int out_size)
{
    const float* ref   = (const float*)d_in[0];
    const float* pred  = (const float*)d_in[1];
    const int*   shell = (const int*)d_in[2];
    float* out = (float*)d_out;

    cudaFuncSetAttribute(k_fft_zy, cudaFuncAttributeMaxDynamicSharedMemorySize, SMEM_BYTES);
    cudaFuncSetAttribute(k_fft_x,  cudaFuncAttributeMaxDynamicSharedMemorySize, SMEM_BYTES);

    void* accPtr = nullptr;
    cudaGetSymbolAddress(&accPtr, g_acc);
    cudaMemsetAsync(accPtr, 0, sizeof(double) * 8 * NSHELL * 3);

    k_fft_zy<<<1024, 256, SMEM_BYTES>>>(ref, pred);
    k_fft_x<<<1024, 256, SMEM_BYTES>>>();
    k_reduce<<<1024, 256>>>(shell);
    k_loss<<<1, 512>>>(out);
}

// round 4
// speedup vs baseline: 4.7184x; 4.7184x over previous
#include <cuda_runtime.h>
#include <math.h>

// ---------------------------------------------------------------------------
// FSC loss: register+shuffle 128-pt FFTs (warp per line), packed complex FFT
// (ref + i*pred), single in-place scratch, on-the-fly shell index.
// Layout after kernel B: plane index pz holds frequency fz = rev7(pz);
// within a plane, natural (fx, fy).
// ---------------------------------------------------------------------------

#define PAD 129
#define SMEM_BYTES (2 * 128 * PAD * 4)   // 132096 B
#define PIF 3.14159265358979323846f

static __device__ float2 g_fft[8u * 128u * 128u * 128u];   // 134 MB scratch
static __device__ double g_acc[8][65][3];                  // num, d1, d2

__device__ __forceinline__ int rev7(int i) { return (int)(__brev((unsigned)i) >> 25); }

// 128-pt DIF FFT: lane t holds points i = t + 32k, k=0..3.
// Natural-order input; output at position i holds X[rev7(i)].
__device__ __forceinline__ void fft128(float re[4], float im[4], int t,
                                       const float2* __restrict__ tw)
{
    // stage stride 64
    {
        float2 w1 = tw[t], w2 = tw[t + 32];
        float ar, ai;
        ar = re[0] - re[2]; ai = im[0] - im[2];
        re[0] += re[2];     im[0] += im[2];
        re[2] = ar * w1.x - ai * w1.y; im[2] = ar * w1.y + ai * w1.x;
        ar = re[1] - re[3]; ai = im[1] - im[3];
        re[1] += re[3];     im[1] += im[3];
        re[3] = ar * w2.x - ai * w2.y; im[3] = ar * w2.y + ai * w2.x;
    }
    // stage stride 32
    {
        float2 w3 = tw[2 * t];
        float ar, ai;
        ar = re[0] - re[1]; ai = im[0] - im[1];
        re[0] += re[1];     im[0] += im[1];
        re[1] = ar * w3.x - ai * w3.y; im[1] = ar * w3.y + ai * w3.x;
        ar = re[2] - re[3]; ai = im[2] - im[3];
        re[2] += re[3];     im[2] += im[3];
        re[3] = ar * w3.x - ai * w3.y; im[3] = ar * w3.y + ai * w3.x;
    }
    // shuffle stages: 4 independent 32-pt FFTs
#pragma unroll
    for (int m = 16; m >= 1; m >>= 1) {
        bool up = (t & m) != 0;
        int idx = up ? (64 / m) * (t & (m - 1)) : 0;
        float2 wm = tw[idx];
#pragma unroll
        for (int k = 0; k < 4; k++) {
            float pr = __shfl_xor_sync(0xffffffffu, re[k], m);
            float pi = __shfl_xor_sync(0xffffffffu, im[k], m);
            float sr = up ? pr - re[k] : re[k] + pr;
            float si = up ? pi - im[k] : im[k] + pi;
            re[k] = sr * wm.x - si * wm.y;
            im[k] = sr * wm.y + si * wm.x;
        }
    }
}

// Kernel A: per (b,x) plane [y][z]. Z-FFT from global into regs, transpose via
// smem, Y-FFT, write g_fft[b][zs][x][ys] (ys contiguous, coalesced).
__global__ __launch_bounds__(512, 1)
void k_fft_zy(const float* __restrict__ ref, const float* __restrict__ pred)
{
    extern __shared__ float sm[];
    float* sRe = sm;
    float* sIm = sm + 128 * PAD;
    __shared__ float2 tw[64];

    int tid = threadIdx.x, t = tid & 31, w = tid >> 5;
    if (tid < 64) {
        float s, c;
        sincosf(-PIF * (float)tid / 64.f, &s, &c);
        tw[tid] = make_float2(c, s);
    }
    __syncthreads();

    int b = blockIdx.x >> 7, x = blockIdx.x & 127;
    size_t base = ((size_t)(b * 128 + x)) << 14;

    // Z pass: warp handles 8 y-lines
    for (int l = 0; l < 8; l++) {
        int y = w * 8 + l;
        float re[4], im[4];
#pragma unroll
        for (int k = 0; k < 4; k++) {
            int z = t + 32 * k;
            re[k] = ref[base + y * 128 + z];
            im[k] = pred[base + y * 128 + z];
        }
        fft128(re, im, t, tw);
#pragma unroll
        for (int k = 0; k < 4; k++) {
            int zs = t + 32 * k;
            sRe[zs * PAD + y] = re[k];      // conflict-free (row = f(lane))
            sIm[zs * PAD + y] = im[k];
        }
    }
    __syncthreads();

    // Y pass: warp handles 8 zs-lines; output straight to global
    for (int l = 0; l < 8; l++) {
        int zs = w * 8 + l;
        float re[4], im[4];
#pragma unroll
        for (int k = 0; k < 4; k++) {
            re[k] = sRe[zs * PAD + t + 32 * k];
            im[k] = sIm[zs * PAD + t + 32 * k];
        }
        fft128(re, im, t, tw);
        size_t rowbase = ((((size_t)(b * 128 + zs)) << 7 | (unsigned)x) << 7);
#pragma unroll
        for (int k = 0; k < 4; k++)
            g_fft[rowbase + t + 32 * k] = make_float2(re[k], im[k]);
    }
}

// Kernel B: per (b,pz) plane [x][ys], fully in-place. X-FFT along rows with
// bit-reversed row write-back (warp-private columns), then store with the
// fy = rev7(ys) column permutation applied. Plane keeps index pz; its
// frequency identity is fz = rev7(pz), resolved in k_reduce.
__global__ __launch_bounds__(512, 1)
void k_fft_x()
{
    extern __shared__ float sm[];
    float* sRe = sm;
    float* sIm = sm + 128 * PAD;
    __shared__ float2 tw[64];

    int tid = threadIdx.x, t = tid & 31, w = tid >> 5;
    if (tid < 64) {
        float s, c;
        sincosf(-PIF * (float)tid / 64.f, &s, &c);
        tw[tid] = make_float2(c, s);
    }

    int b = blockIdx.x >> 7, pz = blockIdx.x & 127;
    float2* __restrict__ plane = g_fft + (((size_t)(b * 128 + pz)) << 14);
    for (int n = tid; n < 16384; n += 512) {
        float2 v = plane[n];
        int x = n >> 7, c = n & 127;
        sRe[x * PAD + c] = v.x;
        sIm[x * PAD + c] = v.y;
    }
    __syncthreads();   // also covers tw init

    // X-FFT: warp owns columns ys = w*8 .. w*8+7; in-place write to own column
    for (int l = 0; l < 8; l++) {
        int ys = w * 8 + l;
        float re[4], im[4];
#pragma unroll
        for (int k = 0; k < 4; k++) {
            re[k] = sRe[(t + 32 * k) * PAD + ys];   // conflict-free
            im[k] = sIm[(t + 32 * k) * PAD + ys];
        }
        fft128(re, im, t, tw);
        __syncwarp();
#pragma unroll
        for (int k = 0; k < 4; k++) {
            int fx = rev7(t + 32 * k);
            sRe[fx * PAD + ys] = re[k];
            sIm[fx * PAD + ys] = im[k];
        }
    }
    __syncthreads();

    // Store back in-place: physical col ys holds freq fy = rev7(ys).
    for (int l = 0; l < 8; l++) {
        int fx = w * 8 + l;
#pragma unroll
        for (int k = 0; k < 4; k++) {
            int fy = t + 32 * k;
            int c = rev7(fy);
            plane[(fx << 7) | fy] = make_float2(sRe[fx * PAD + c], sIm[fx * PAD + c]);
        }
    }
}

// Kernel C: Hermitian unpack + shell accumulation.
// Plane pz <-> freq fz = rev7(pz); partner plane pzn = rev7((128-fz)&127).
__global__ __launch_bounds__(512)
void k_reduce()
{
    __shared__ float bins[3 * 65 * 32];   // [comp][shell][lane]
    int tid = threadIdx.x, lane = tid & 31;
    for (int i = tid; i < 3 * 65 * 32; i += 512) bins[i] = 0.f;
    __syncthreads();

    int b = blockIdx.x >> 7, pz = blockIdx.x & 127;
    int fz  = rev7(pz);
    int fzn = (128 - fz) & 127;
    int pzn = rev7(fzn);
    int szv = min(fz, 128 - fz);
    const float2* __restrict__ P  = g_fft + (((size_t)(b * 128 + pz )) << 14);
    const float2* __restrict__ Pn = g_fft + (((size_t)(b * 128 + pzn)) << 14);

    for (int n = tid; n < 16384; n += 512) {
        int fx = n >> 7, fy = n & 127;
        int fxn = (128 - fx) & 127, fyn = (128 - fy) & 127;
        float2 Gk = P[n];
        float2 Gm = Pn[(fxn << 7) | fyn];
        // A = 2*F1 ; B = 2i*F2 — common x4 scale cancels in FSC
        float ar = Gk.x + Gm.x, ai = Gk.y - Gm.y;
        float br = Gk.x - Gm.x, bi = Gk.y + Gm.y;
        float cross = ar * bi - ai * br;
        float p1 = ar * ar + ai * ai;
        float p2 = br * br + bi * bi;
        int sx = min(fx, 128 - fx), sy = min(fy, 128 - fy);
        int r2 = sx * sx + sy * sy + szv * szv;
        int s = min(64, (int)sqrtf((float)r2));
        atomicAdd(&bins[(0 * 65 + s) * 32 + lane], cross);
        atomicAdd(&bins[(1 * 65 + s) * 32 + lane], p1);
        atomicAdd(&bins[(2 * 65 + s) * 32 + lane], p2);
    }
    __syncthreads();

    for (int i = tid; i < 3 * 65; i += 512) {
        float acc = 0.f;
#pragma unroll
        for (int j = 0; j < 32; j++) acc += bins[i * 32 + j];
        int comp = i / 65, s = i % 65;
        if (s < 64) atomicAdd(&g_acc[b][s][comp], (double)acc);
    }
}

// Kernel D: loss = 1 - mean_{b,s<64}(fsc^2)
__global__ __launch_bounds__(512)
void k_loss(float* __restrict__ out)
{
    __shared__ double ssum[512];
    int t = threadIdx.x;
    int b = t >> 6, s = t & 63;
    double num = g_acc[b][s][0];
    double d1  = g_acc[b][s][1];
    double d2  = g_acc[b][s][2];
    double fsc = num / (sqrt(d1 * d2) + 1e-8);
    ssum[t] = fsc * fsc;
    __syncthreads();
    for (int off = 256; off > 0; off >>= 1) {
        if (t < off) ssum[t] += ssum[t + off];
        __syncthreads();
    }
    if (t == 0) out[0] = (float)(1.0 - ssum[0] / 512.0);
}

extern "C" void kernel_launch(void* const* d_in, const int* in_sizes, int n_in,
                              void* d_out, int out_size)
{
    const float* ref  = (const float*)d_in[0];
    const float* pred = (const float*)d_in[1];
    float* out = (float*)d_out;

    cudaFuncSetAttribute(k_fft_zy, cudaFuncAttributeMaxDynamicSharedMemorySize, SMEM_BYTES);
    cudaFuncSetAttribute(k_fft_x,  cudaFuncAttributeMaxDynamicSharedMemorySize, SMEM_BYTES);

    void* accPtr = nullptr;
    cudaGetSymbolAddress(&accPtr, g_acc);
    cudaMemsetAsync(accPtr, 0, sizeof(double) * 8 * 65 * 3);

    k_fft_zy<<<1024, 512, SMEM_BYTES>>>(ref, pred);
    k_fft_x<<<1024, 512, SMEM_BYTES>>>();
    k_reduce<<<1024, 512>>>();
    k_loss<<<1, 512>>>(out);
}